// round 1
// baseline (speedup 1.0000x reference)
#include <cuda_runtime.h>

#define NB   32
#define CINC 32
#define COUTC 32
#define HWD  128
#define CONDD 256
#define HIDD 4608
#define NPARAM 9216            // per-sample conv params (32*32*3*3)
#define KSPLIT 4
#define KCHUNK 1152            // HIDD / KSPLIT

// Scratch (device globals: allocation-free rule)
__device__ float g_ht[HIDD * NB];                 // h transposed [hid][b]
__device__ float g_part[KSPLIT * NB * NPARAM];    // gemm2 k-split partials
__device__ float g_w[NB * NPARAM];                // final per-sample weights

// ---------------------------------------------------------------------------
// Kernel 1: h = relu(cond @ W1^T + b1), stored transposed ht[hid][b]
// ---------------------------------------------------------------------------
__global__ void mlp1_kernel(const float* __restrict__ cond,
                            const float* __restrict__ W1,
                            const float* __restrict__ b1) {
    int idx = blockIdx.x * blockDim.x + threadIdx.x;   // 147456 threads
    int hid = idx >> 5;
    int b   = idx & 31;
    const float4* c4 = (const float4*)(cond + b * CONDD);
    const float4* w4 = (const float4*)(W1 + (size_t)hid * CONDD);
    float acc = b1[hid];
#pragma unroll 8
    for (int i = 0; i < CONDD / 4; i++) {
        float4 cv = c4[i];
        float4 wv = w4[i];
        acc += cv.x * wv.x + cv.y * wv.y + cv.z * wv.z + cv.w * wv.w;
    }
    g_ht[hid * 32 + b] = fmaxf(acc, 0.0f);
}

// ---------------------------------------------------------------------------
// Kernel 2: partial[kc][b][p] = sum_{k in chunk kc} ht[k][b] * W2[p][k]
// Tile: 32b x 128p, K-chunk 1152. 256 threads, micro-tile 4b x 4p.
// ---------------------------------------------------------------------------
__global__ void gemm2_kernel(const float* __restrict__ W2) {
    __shared__ float s_h[32 * 32];       // [kk][b]
    __shared__ float s_w[32 * 132];      // [kk][p] padded row stride 132

    int t     = threadIdx.x;
    int pbase = blockIdx.x * 128;
    int kc    = blockIdx.y;

    int b0 = (t & 7) * 4;
    int p0 = (t >> 3) * 4;

    float acc[4][4];
#pragma unroll
    for (int i = 0; i < 4; i++)
#pragma unroll
        for (int j = 0; j < 4; j++) acc[i][j] = 0.0f;

    const float4* ht4 = (const float4*)g_ht;
    const float4* W24 = (const float4*)W2;

    for (int ks = 0; ks < KCHUNK; ks += 32) {
        int kbase = kc * KCHUNK + ks;

        // load s_h: 32 k-rows x 32 b (one float4 per thread)
        {
            int kk  = t >> 3;
            int c4i = t & 7;
            ((float4*)s_h)[t] = ht4[(kbase + kk) * 8 + c4i];
        }
        // load s_w transposed: W2[p][k] -> s_w[k][p]
#pragma unroll
        for (int i = 0; i < 4; i++) {
            int j  = t + i * 256;
            int p  = j >> 3;
            int k4 = j & 7;
            float4 v = W24[(size_t)(pbase + p) * 1152 + (kbase >> 2) + k4];
            s_w[(k4 * 4 + 0) * 132 + p] = v.x;
            s_w[(k4 * 4 + 1) * 132 + p] = v.y;
            s_w[(k4 * 4 + 2) * 132 + p] = v.z;
            s_w[(k4 * 4 + 3) * 132 + p] = v.w;
        }
        __syncthreads();

#pragma unroll
        for (int kk = 0; kk < 32; kk++) {
            float4 hv = *(const float4*)&s_h[kk * 32 + b0];
            float4 wv = *(const float4*)&s_w[kk * 132 + p0];
            float hb[4] = {hv.x, hv.y, hv.z, hv.w};
            float wp[4] = {wv.x, wv.y, wv.z, wv.w};
#pragma unroll
            for (int i = 0; i < 4; i++)
#pragma unroll
                for (int j = 0; j < 4; j++) acc[i][j] += hb[i] * wp[j];
        }
        __syncthreads();
    }

    float* dst = g_part + (size_t)kc * (NB * NPARAM);
#pragma unroll
    for (int i = 0; i < 4; i++) {
        float4 v = make_float4(acc[i][0], acc[i][1], acc[i][2], acc[i][3]);
        *(float4*)&dst[(size_t)(b0 + i) * NPARAM + pbase + p0] = v;
    }
}

// ---------------------------------------------------------------------------
// Kernel 3: reduce k-split partials + bias -> g_w[b][p]
// ---------------------------------------------------------------------------
__global__ void reduce_kernel(const float* __restrict__ b2) {
    int idx = blockIdx.x * blockDim.x + threadIdx.x;   // < 294912
    const int n = NB * NPARAM;
    float s = g_part[idx] + g_part[idx + n] + g_part[idx + 2 * n] +
              g_part[idx + 3 * n];
    g_w[idx] = s + b2[idx % NPARAM];
}

// ---------------------------------------------------------------------------
// Kernel 4: per-sample 3x3 conv (pad 1, stride 1).
// Block: (b, 8y x 64x slab), all 32 cout. 256 threads, micro 4co x 2y x 8x.
// Smem: x tile 32ch x 10 x 66 (halo) + weights transposed [cin*9+q][co].
// ---------------------------------------------------------------------------
#define SX_SZ (32 * 10 * 66)     // 21120 floats
#define SW_SZ (288 * 32)         // 9216 floats

__global__ void __launch_bounds__(256, 1)
conv_kernel(const float* __restrict__ x, float* __restrict__ out) {
    extern __shared__ float smem[];
    float* s_x = smem;               // [cin][row 0..9][col 0..65]
    float* s_w = smem + SX_SZ;       // [cin*9 + ky*3 + kx][co]

    int t   = threadIdx.x;
    int b   = blockIdx.z;
    int gy0 = blockIdx.y * 8;
    int gx0 = blockIdx.x * 64;

    // load per-sample weights, transposing to co-contiguous
    const float* wsrc = g_w + (size_t)b * NPARAM;
    for (int i = t; i < NPARAM; i += 256) {
        int co = i / 288;
        int q  = i - co * 288;       // cin*9 + ky*3 + kx
        s_w[q * 32 + co] = wsrc[i];
    }

    // load x tile with halo (zero pad at image edges)
    for (int i = t; i < SX_SZ; i += 256) {
        int cin = i / 660;
        int rem = i - cin * 660;
        int row = rem / 66;
        int col = rem - row * 66;
        int gy = gy0 - 1 + row;
        int gx = gx0 - 1 + col;
        float v = 0.0f;
        if (gy >= 0 && gy < HWD && gx >= 0 && gx < HWD)
            v = x[(((size_t)b * 32 + cin) * HWD + gy) * HWD + gx];
        s_x[i] = v;
    }
    __syncthreads();

    int co0 = (t & 7) * 4;
    int g   = t >> 3;
    int y0  = (g >> 3) * 2;
    int x0  = (g & 7) * 8;

    float acc[4][2][8];
#pragma unroll
    for (int c = 0; c < 4; c++)
#pragma unroll
        for (int my = 0; my < 2; my++)
#pragma unroll
            for (int xx = 0; xx < 8; xx++) acc[c][my][xx] = 0.0f;

    for (int cin = 0; cin < 32; cin++) {
        const float* xb = s_x + cin * 660;
#pragma unroll
        for (int ky = 0; ky < 3; ky++) {
            float a0[10], a1[10];
            const float* pr = xb + (y0 + ky) * 66 + x0;
#pragma unroll
            for (int j = 0; j < 10; j++) {
                a0[j] = pr[j];
                a1[j] = pr[66 + j];
            }
            const float* wq = s_w + (cin * 9 + ky * 3) * 32 + co0;
            float4 w0 = *(const float4*)(wq);
            float4 w1 = *(const float4*)(wq + 32);
            float4 w2 = *(const float4*)(wq + 64);
            float wc0[4] = {w0.x, w0.y, w0.z, w0.w};
            float wc1[4] = {w1.x, w1.y, w1.z, w1.w};
            float wc2[4] = {w2.x, w2.y, w2.z, w2.w};
#pragma unroll
            for (int c = 0; c < 4; c++) {
#pragma unroll
                for (int xx = 0; xx < 8; xx++) {
                    acc[c][0][xx] += wc0[c] * a0[xx];
                    acc[c][0][xx] += wc1[c] * a0[xx + 1];
                    acc[c][0][xx] += wc2[c] * a0[xx + 2];
                    acc[c][1][xx] += wc0[c] * a1[xx];
                    acc[c][1][xx] += wc1[c] * a1[xx + 1];
                    acc[c][1][xx] += wc2[c] * a1[xx + 2];
                }
            }
        }
    }

#pragma unroll
    for (int c = 0; c < 4; c++) {
#pragma unroll
        for (int my = 0; my < 2; my++) {
            float* po = out +
                ((size_t)(b * 32 + co0 + c) * HWD + (gy0 + y0 + my)) * HWD +
                gx0 + x0;
            float4 v0 = make_float4(acc[c][my][0], acc[c][my][1],
                                    acc[c][my][2], acc[c][my][3]);
            float4 v1 = make_float4(acc[c][my][4], acc[c][my][5],
                                    acc[c][my][6], acc[c][my][7]);
            *(float4*)(po)     = v0;
            *(float4*)(po + 4) = v1;
        }
    }
}

// ---------------------------------------------------------------------------
extern "C" void kernel_launch(void* const* d_in, const int* in_sizes, int n_in,
                              void* d_out, int out_size) {
    const float* x    = (const float*)d_in[0];
    const float* cond = (const float*)d_in[1];
    const float* W1   = (const float*)d_in[2];
    const float* b1   = (const float*)d_in[3];
    const float* W2   = (const float*)d_in[4];
    const float* b2   = (const float*)d_in[5];
    float* out = (float*)d_out;

    const int conv_smem = (SX_SZ + SW_SZ) * sizeof(float);   // 121344 B
    cudaFuncSetAttribute(conv_kernel,
                         cudaFuncAttributeMaxDynamicSharedMemorySize,
                         conv_smem);

    mlp1_kernel<<<(HIDD * NB) / 256, 256>>>(cond, W1, b1);
    gemm2_kernel<<<dim3(NPARAM / 128, KSPLIT), 256>>>(W2);
    reduce_kernel<<<(NB * NPARAM) / 256, 256>>>(b2);
    conv_kernel<<<dim3(HWD / 64, HWD / 8, NB), 256, conv_smem>>>(x, out);
}